// round 5
// baseline (speedup 1.0000x reference)
#include <cuda_runtime.h>

// knnLoss via exact 1-D spatially-pruned KNN.
// Pipeline: init hists -> histogram(x-bin) -> prefix+guards -> counting scatter
//           -> warp-per-32-sorted-queries outward scan with provable pruning
//           -> fixed-point deterministic reduction.

#define NPTS    16384
#define NB      2
#define NBINS   512
#define XMIN    (-4.5f)
#define BINSCL  (NBINS / 9.0f)
#define WBIN    (9.0f / NBINS)
#define PAD     64
#define TOT     (NPTS + 2 * PAD)        // 16512
#define NTASK   512                     // warp-tasks per batch (32 queries each)
#define SCANBLK 128
#define SCANTHR 256

__device__ int       g_thist[NB * NBINS];
__device__ int       g_qhist[NB * NBINS];
__device__ int       g_tbase[NB * NBINS];
__device__ int       g_tcur [NB * NBINS];
__device__ int       g_qcur [NB * NBINS];
__device__ float     g_sx[NB * TOT];
__device__ float     g_sy[NB * TOT];
__device__ float     g_sz[NB * TOT];
__device__ float     g_sw[NB * TOT];
__device__ float4    g_q [NB * NPTS];
__device__ long long g_psum[NB * NTASK];
__device__ int       g_pcnt[NB * NTASK];

#define FMA2(d, a, b, c) \
    asm("fma.rn.f32x2 %0, %1, %2, %3;" : "=l"(d) : "l"(a), "l"(b), "l"(c))
#define UNPK2(lo, hi, v) \
    asm("mov.b64 {%0, %1}, %2;" : "=f"(lo), "=f"(hi) : "l"(v))
#define PK2(d, lo, hi) \
    asm("mov.b64 %0, {%1, %2};" : "=l"(d) : "f"(lo), "f"(hi))
#define DUP2(d, f) \
    asm("mov.b64 %0, {%1, %1};" : "=l"(d) : "f"(f))

__device__ __forceinline__ int xbin(float x) {
    int b = (int)((x - XMIN) * BINSCL);
    return min(max(b, 0), NBINS - 1);
}

__device__ __forceinline__ void top3_insert(float r, float& b0, float& b1, float& b2) {
    float m1 = fmaxf(r, b1);
    float m0 = fmaxf(r, b0);
    b2 = fminf(b2, m1);
    b1 = fminf(b1, m0);
    b0 = fminf(b0, r);
}

__global__ void init_kernel() {
    int t = threadIdx.x;
    if (t < NB * NBINS) { g_thist[t] = 0; g_qhist[t] = 0; }
}

__global__ void hist_kernel(const float* __restrict__ src,
                            const float* __restrict__ tgt) {
    int i = blockIdx.x * blockDim.x + threadIdx.x;   // 0 .. NB*NPTS-1
    int b = i >> 14;
    int n = i & (NPTS - 1);
    int h = n >> 9;
    int w = n & 511;
    // query x: source_pc [B,64,2048,3] at [b,2h,4w,0]
    long sb = (((long)b * 64 + 2 * h) * 2048 + 4 * w) * 3;
    float sx = src[sb];
    // target x: target_pc [B,3,64,2048] at [b,0,2h,4w]  (invalid -> all zero -> x=0 anyway)
    long tb = (long)b * 3 * 64 * 2048 + (long)(2 * h) * 2048 + 4 * w;
    float tx = tgt[tb];
    atomicAdd(&g_thist[b * NBINS + xbin(tx)], 1);
    atomicAdd(&g_qhist[b * NBINS + xbin(sx)], 1);
}

__global__ __launch_bounds__(NBINS) void prefix_kernel() {
    __shared__ int sh[NBINS];
    int t = threadIdx.x;
    for (int a = 0; a < 4; a++) {
        int v = (a < 2) ? g_thist[a * NBINS + t] : g_qhist[(a - 2) * NBINS + t];
        sh[t] = v;
        __syncthreads();
        for (int o = 1; o < NBINS; o <<= 1) {
            int u = (t >= o) ? sh[t - o] : 0;
            __syncthreads();
            sh[t] += u;
            __syncthreads();
        }
        int excl = sh[t] - v;
        if (a < 2) {
            g_tbase[a * NBINS + t] = excl;
            g_tcur [a * NBINS + t] = excl;
        } else {
            g_qcur[(a - 2) * NBINS + t] = excl;
        }
        __syncthreads();
    }
    // guard padding: far-away sentinels that prune naturally and never win
    for (int i = t; i < NB * 2 * PAD; i += blockDim.x) {
        int b = i / (2 * PAD);
        int j = i % (2 * PAD);
        int slot;
        float gx;
        if (j < PAD) { slot = b * TOT + j;              gx = -1e9f; }
        else         { slot = b * TOT + PAD + NPTS + (j - PAD); gx = 1e9f; }
        g_sx[slot] = gx; g_sy[slot] = 0.0f; g_sz[slot] = 0.0f; g_sw[slot] = 1e30f;
    }
}

__global__ void scatter_kernel(const float* __restrict__ src,
                               const float* __restrict__ tgt) {
    int i = blockIdx.x * blockDim.x + threadIdx.x;
    int b = i >> 14;
    int n = i & (NPTS - 1);
    int h = n >> 9;
    int w = n & 511;

    // target
    long tb = (long)b * 3 * 64 * 2048 + (long)(2 * h) * 2048 + 4 * w;
    float tx = tgt[tb];
    float ty = tgt[tb + 64 * 2048];
    float tz = tgt[tb + 2L * 64 * 2048];
    bool  vt = (tx != 0.0f) || (ty != 0.0f) || (tz != 0.0f);
    float tw;
    if (vt) tw = tx * tx + ty * ty + tz * tz;
    else { tx = 0.0f; ty = 0.0f; tz = 0.0f; tw = 1e20f; }
    int tpos = PAD + atomicAdd(&g_tcur[b * NBINS + xbin(tx)], 1);
    int ts = b * TOT + tpos;
    g_sx[ts] = tx; g_sy[ts] = ty; g_sz[ts] = tz; g_sw[ts] = tw;

    // query
    long sb = (((long)b * 64 + 2 * h) * 2048 + 4 * w) * 3;
    float sx = src[sb + 0];
    float sy = src[sb + 1];
    float sz = src[sb + 2];
    bool  vs = (sx != 0.0f) || (sy != 0.0f) || (sz != 0.0f);
    float sq = sx * sx + sy * sy + sz * sz;
    int qpos = atomicAdd(&g_qcur[b * NBINS + xbin(sx)], 1);
    g_q[b * NPTS + qpos] = make_float4(-2.0f * sx, -2.0f * sy, -2.0f * sz,
                                       vs ? sq : -1.0f);
}

__global__ __launch_bounds__(SCANTHR) void scan_kernel() {
    int warp = threadIdx.x >> 5;
    int lane = threadIdx.x & 31;
    int task = blockIdx.x + SCANBLK * warp;          // 0..1023, interleaved for balance
    int b    = task >> 9;
    int qc   = task & (NTASK - 1);

    float4 q  = g_q[b * NPTS + qc * 32 + lane];
    float  xq = -0.5f * q.x;
    float  sq = fmaxf(q.w, 0.0f);
    float  wgt = (q.w >= 0.0f) ? 1.0f : 0.0f;

    unsigned long long qx, qy, qz;
    DUP2(qx, q.x); DUP2(qy, q.y); DUP2(qz, q.z);

    int mybin = xbin(xq);
    int bin15 = __shfl_sync(0xffffffffu, mybin, 15);
    int bOff  = b * TOT;
    int start = bOff + PAD + g_tbase[b * NBINS + bin15];
    int R = start & ~3;
    int L = R - 4;

    const float4* px = (const float4*)(g_sx + bOff);
    const float4* py = (const float4*)(g_sy + bOff);
    const float4* pz = (const float4*)(g_sz + bOff);
    const float4* pw = (const float4*)(g_sw + bOff);

    float b0 = 3e38f, b1 = 3e38f, b2 = 3e38f;
    unsigned act = 3u;   // bit0 = right active, bit1 = left active
    int tog = 0;

    while (act) {
        bool useR = (act & 1u) && (!(act & 2u) || !(tog & 1));
        tog++;
        int idx = useR ? R : L;
        int c   = (idx - bOff) >> 2;

        float4 xv = __ldg(px + c);
        float4 yv = __ldg(py + c);
        float4 zv = __ldg(pz + c);
        float4 wv = __ldg(pw + c);

        unsigned long long xp0, xp1, yp0, yp1, zp0, zp1, wp0, wp1;
        PK2(xp0, xv.x, xv.y); PK2(xp1, xv.z, xv.w);
        PK2(yp0, yv.x, yv.y); PK2(yp1, yv.z, yv.w);
        PK2(zp0, zv.x, zv.y); PK2(zp1, zv.z, zv.w);
        PK2(wp0, wv.x, wv.y); PK2(wp1, wv.z, wv.w);

        unsigned long long rA, rB;
        FMA2(rA, qx, xp0, wp0);
        FMA2(rB, qx, xp1, wp1);
        FMA2(rA, qy, yp0, rA);
        FMA2(rB, qy, yp1, rB);
        FMA2(rA, qz, zp0, rA);
        FMA2(rB, qz, zp1, rB);

        float r0, r1, r2, r3;
        UNPK2(r0, r1, rA);
        UNPK2(r2, r3, rB);
        float m = fminf(fminf(r0, r1), fminf(r2, r3));
        if (m < b2) {
            top3_insert(r0, b0, b1, b2);
            top3_insert(r1, b0, b1, b2);
            top3_insert(r2, b0, b1, b2);
            top3_insert(r3, b0, b1, b2);
        }

        if (useR) {
            R += 4;
            // remaining right elements have x >= binLeft(bin(xv.w)) >= xv.w - WBIN
            float dd = (xv.w - WBIN) - xq;
            bool done = (dd > 0.0f) && (dd * dd >= b2 + sq);
            if (__all_sync(0xffffffffu, done) || (R + 4 > bOff + TOT)) act &= ~1u;
        } else {
            L -= 4;
            // remaining left elements have x <= binRight(bin(xv.x)) <= xv.x + WBIN
            float dd = xq - (xv.x + WBIN);
            bool done = (dd > 0.0f) && (dd * dd >= b2 + sq);
            if (__all_sync(0xffffffffu, done) || (L < bOff)) act &= ~2u;
        }
    }

    float dsum = sqrtf(fmaxf(b0 + sq, 0.0f))
               + sqrtf(fmaxf(b1 + sq, 0.0f))
               + sqrtf(fmaxf(b2 + sq, 0.0f));

    // fixed-point (x 2^32) => grouping-invariant deterministic accumulation
    long long v = __float2ll_rn(fminf(wgt * dsum, 1e6f) * 4294967296.0f);
#pragma unroll
    for (int o = 16; o; o >>= 1)
        v += __shfl_down_sync(0xffffffffu, v, o);
    int cnt = __popc(__ballot_sync(0xffffffffu, wgt > 0.0f));
    if (lane == 0) {
        g_psum[task] = v;
        g_pcnt[task] = cnt;
    }
}

__global__ __launch_bounds__(NTASK) void final_kernel(float* __restrict__ out) {
    __shared__ long long s0[NTASK], s1[NTASK];
    __shared__ int c0[NTASK], c1[NTASK];
    int t = threadIdx.x;
    s0[t] = g_psum[t];          c0[t] = g_pcnt[t];
    s1[t] = g_psum[NTASK + t];  c1[t] = g_pcnt[NTASK + t];
    __syncthreads();
    for (int o = NTASK / 2; o; o >>= 1) {
        if (t < o) {
            s0[t] += s0[t + o]; s1[t] += s1[t + o];
            c0[t] += c0[t + o]; c1[t] += c1[t + o];
        }
        __syncthreads();
    }
    if (t == 0) {
        double S0 = (double)s0[0] / 4294967296.0;
        double S1 = (double)s1[0] / 4294967296.0;
        float l0 = (float)(S0 / (3.0 * (double)max(c0[0], 1)));
        float l1 = (float)(S1 / (3.0 * (double)max(c1[0], 1)));
        out[0] = 0.5f * (l0 + l1);
    }
}

extern "C" void kernel_launch(void* const* d_in, const int* in_sizes, int n_in,
                              void* d_out, int out_size) {
    const float* src = (const float*)d_in[0];   // source_pc [2,64,2048,3]
    const float* tgt = (const float*)d_in[1];   // target_pc [2,3,64,2048]

    init_kernel<<<1, 1024>>>();
    hist_kernel<<<NB * NPTS / 256, 256>>>(src, tgt);
    prefix_kernel<<<1, NBINS>>>();
    scatter_kernel<<<NB * NPTS / 256, 256>>>(src, tgt);
    scan_kernel<<<SCANBLK, SCANTHR>>>();
    final_kernel<<<1, NTASK>>>((float*)d_out);
}

// round 6
// speedup vs baseline: 2.7467x; 2.7467x over previous
#include <cuda_runtime.h>

// knnLoss via exact x-sorted tile-pruned KNN.
// init hists -> histogram(x-bin) -> prefix -> counting scatter (targets SoA + queries)
// -> per-block outward tile scan with block-consensus pruning -> deterministic reduce.

#define NPTS   16384
#define NB     2
#define NBINS  512
#define XMIN   (-4.5f)
#define BINSCL (NBINS / 9.0f)
#define WBIN   (9.0f / NBINS)
#define TILE   512
#define NTILES (NPTS / TILE)     // 32
#define QBLK   256               // queries per scan block
#define NSCAN  (NB * NPTS / QBLK) // 128 scan blocks

__device__ int       g_thist[NB * NBINS];
__device__ int       g_qhist[NB * NBINS];
__device__ int       g_tbase[NB * NBINS];
__device__ int       g_tcur [NB * NBINS];
__device__ int       g_qcur [NB * NBINS];
__device__ float     g_sx[NB * NPTS];
__device__ float     g_sy[NB * NPTS];
__device__ float     g_sz[NB * NPTS];
__device__ float     g_sw[NB * NPTS];
__device__ float4    g_q [NB * NPTS];
__device__ long long g_psum[NSCAN];
__device__ int       g_pcnt[NSCAN];

#define FMA2(d, a, b, c) \
    asm("fma.rn.f32x2 %0, %1, %2, %3;" : "=l"(d) : "l"(a), "l"(b), "l"(c))
#define UNPK2(lo, hi, v) \
    asm("mov.b64 {%0, %1}, %2;" : "=f"(lo), "=f"(hi) : "l"(v))
#define DUP2(d, f) \
    asm("mov.b64 %0, {%1, %1};" : "=l"(d) : "f"(f))

__device__ __forceinline__ int xbin(float x) {
    int b = (int)((x - XMIN) * BINSCL);
    return min(max(b, 0), NBINS - 1);
}

__device__ __forceinline__ void top3_insert(float r, float& b0, float& b1, float& b2) {
    float m1 = fmaxf(r, b1);
    float m0 = fmaxf(r, b0);
    b2 = fminf(b2, m1);
    b1 = fminf(b1, m0);
    b0 = fminf(b0, r);
}

__global__ void init_kernel() {
    int t = threadIdx.x;
    if (t < NB * NBINS) { g_thist[t] = 0; g_qhist[t] = 0; }
}

__global__ void hist_kernel(const float* __restrict__ src,
                            const float* __restrict__ tgt) {
    int i = blockIdx.x * blockDim.x + threadIdx.x;   // 0 .. NB*NPTS-1
    int b = i >> 14;
    int n = i & (NPTS - 1);
    int h = n >> 9;
    int w = n & 511;
    long sb = (((long)b * 64 + 2 * h) * 2048 + 4 * w) * 3;
    float sx = src[sb];
    long tb = (long)b * 3 * 64 * 2048 + (long)(2 * h) * 2048 + 4 * w;
    float tx = tgt[tb];
    atomicAdd(&g_thist[b * NBINS + xbin(tx)], 1);
    atomicAdd(&g_qhist[b * NBINS + xbin(sx)], 1);
}

__global__ __launch_bounds__(NBINS) void prefix_kernel() {
    __shared__ int sh[NBINS];
    int t = threadIdx.x;
    for (int a = 0; a < 4; a++) {
        int v = (a < 2) ? g_thist[a * NBINS + t] : g_qhist[(a - 2) * NBINS + t];
        sh[t] = v;
        __syncthreads();
        for (int o = 1; o < NBINS; o <<= 1) {
            int u = (t >= o) ? sh[t - o] : 0;
            __syncthreads();
            sh[t] += u;
            __syncthreads();
        }
        int excl = sh[t] - v;
        if (a < 2) {
            g_tbase[a * NBINS + t] = excl;
            g_tcur [a * NBINS + t] = excl;
        } else {
            g_qcur[(a - 2) * NBINS + t] = excl;
        }
        __syncthreads();
    }
}

__global__ void scatter_kernel(const float* __restrict__ src,
                               const float* __restrict__ tgt) {
    int i = blockIdx.x * blockDim.x + threadIdx.x;
    int b = i >> 14;
    int n = i & (NPTS - 1);
    int h = n >> 9;
    int w = n & 511;

    // target -> sorted SoA
    long tb = (long)b * 3 * 64 * 2048 + (long)(2 * h) * 2048 + 4 * w;
    float tx = tgt[tb];
    float ty = tgt[tb + 64 * 2048];
    float tz = tgt[tb + 2L * 64 * 2048];
    bool  vt = (tx != 0.0f) || (ty != 0.0f) || (tz != 0.0f);
    float tw;
    if (vt) tw = tx * tx + ty * ty + tz * tz;
    else { tx = 0.0f; ty = 0.0f; tz = 0.0f; tw = 1e20f; }
    int tpos = atomicAdd(&g_tcur[b * NBINS + xbin(tx)], 1);
    int ts = b * NPTS + tpos;
    g_sx[ts] = tx; g_sy[ts] = ty; g_sz[ts] = tz; g_sw[ts] = tw;

    // query -> sorted packed
    long sb = (((long)b * 64 + 2 * h) * 2048 + 4 * w) * 3;
    float sx = src[sb + 0];
    float sy = src[sb + 1];
    float sz = src[sb + 2];
    bool  vs = (sx != 0.0f) || (sy != 0.0f) || (sz != 0.0f);
    float sq = sx * sx + sy * sy + sz * sz;
    int qpos = atomicAdd(&g_qcur[b * NBINS + xbin(sx)], 1);
    g_q[b * NPTS + qpos] = make_float4(-2.0f * sx, -2.0f * sy, -2.0f * sz,
                                       vs ? sq : -1.0f);
}

__global__ __launch_bounds__(QBLK) void scan_kernel() {
    __shared__ ulonglong2 s_x[TILE / 4];
    __shared__ ulonglong2 s_y[TILE / 4];
    __shared__ ulonglong2 s_z[TILE / 4];
    __shared__ ulonglong2 s_w[TILE / 4];
    __shared__ float sh_xlo, sh_xhi;
    __shared__ int   sh_home;

    int tid = threadIdx.x;
    int b   = blockIdx.x >> 6;                 // 64 blocks per batch
    int qi  = b * NPTS + (blockIdx.x & 63) * QBLK + tid;

    float4 s  = g_q[qi];
    float  xq = -0.5f * s.x;
    bool   valid = (s.w >= 0.0f);
    float  sq = fmaxf(s.w, 0.0f);

    unsigned long long qx, qy, qz;
    DUP2(qx, s.x); DUP2(qy, s.y); DUP2(qz, s.z);

    if (tid == QBLK / 2) {
        int pos = g_tbase[b * NBINS + xbin(xq)];
        sh_home = min(pos >> 9, NTILES - 1);
    }
    __syncthreads();

    int  tR = sh_home, tL = sh_home - 1;
    bool aR = true, aL = (tL >= 0);
    int  tog = 0;
    float b0 = 3e38f, b1 = 3e38f, b2 = 3e38f;

    while (aR || aL) {
        bool useR = aR && (!aL || !(tog & 1));
        tog++;
        int t    = useR ? tR : tL;
        int base = b * NPTS + t * TILE;

        if (tid == 0) {
            int binf = xbin(g_sx[base]);
            int binl = xbin(g_sx[base + TILE - 1]);
            sh_xlo = XMIN + binf * WBIN;
            sh_xhi = XMIN + (binl + 1) * WBIN;
        }
        __syncthreads();
        float xlo = sh_xlo, xhi = sh_xhi;

        float rq   = sqrtf(fmaxf(b2 + sq, 0.0f));
        bool  need = valid && (xq + rq >= xlo) && (xq - rq <= xhi);

        if (__syncthreads_or(need)) {
            const float4* px = (const float4*)(g_sx + base);
            const float4* py = (const float4*)(g_sy + base);
            const float4* pz = (const float4*)(g_sz + base);
            const float4* pw = (const float4*)(g_sw + base);
            if (tid < TILE / 4) {
                float4 vx = px[tid]; s_x[tid] = *(const ulonglong2*)&vx;
                float4 vy = py[tid]; s_y[tid] = *(const ulonglong2*)&vy;
            } else {
                int i2 = tid - TILE / 4;
                float4 vz = pz[i2]; s_z[i2] = *(const ulonglong2*)&vz;
                float4 vw = pw[i2]; s_w[i2] = *(const ulonglong2*)&vw;
            }
            __syncthreads();

#pragma unroll 4
            for (int j = 0; j < TILE / 4; j++) {
                ulonglong2 xv = s_x[j];
                ulonglong2 yv = s_y[j];
                ulonglong2 zv = s_z[j];
                ulonglong2 wv = s_w[j];
                unsigned long long rA, rB;
                FMA2(rA, qx, xv.x, wv.x);
                FMA2(rB, qx, xv.y, wv.y);
                FMA2(rA, qy, yv.x, rA);
                FMA2(rB, qy, yv.y, rB);
                FMA2(rA, qz, zv.x, rA);
                FMA2(rB, qz, zv.y, rB);
                float r0, r1, r2, r3;
                UNPK2(r0, r1, rA);
                UNPK2(r2, r3, rB);
                float m = fminf(fminf(r0, r1), fminf(r2, r3));
                if (m < b2) {
                    top3_insert(r0, b0, b1, b2);
                    top3_insert(r1, b0, b1, b2);
                    top3_insert(r2, b0, b1, b2);
                    top3_insert(r3, b0, b1, b2);
                }
            }
            __syncthreads();
            rq = sqrtf(fmaxf(b2 + sq, 0.0f));
        }

        if (useR) {
            // remaining right tiles have x >= xhi - WBIN
            bool cont = valid && (xq + rq >= xhi - WBIN);
            int  any  = __syncthreads_or(cont);
            tR++;
            aR = any && (tR < NTILES);
        } else {
            // remaining left tiles have x <= xlo + WBIN
            bool cont = valid && (xq - rq <= xlo + WBIN);
            int  any  = __syncthreads_or(cont);
            tL--;
            aL = any && (tL >= 0);
        }
    }

    float wgt  = valid ? 1.0f : 0.0f;
    float dsum = sqrtf(fmaxf(b0 + sq, 0.0f))
               + sqrtf(fmaxf(b1 + sq, 0.0f))
               + sqrtf(fmaxf(b2 + sq, 0.0f));

    // fixed-point (x 2^32): deterministic, order-invariant accumulation
    long long v = __float2ll_rn(fminf(wgt * dsum, 1e5f) * 4294967296.0f);
#pragma unroll
    for (int o = 16; o; o >>= 1)
        v += __shfl_down_sync(0xffffffffu, v, o);

    __shared__ long long wsum[QBLK / 32];
    __shared__ int       wcnt[QBLK / 32];
    int lane = tid & 31, warp = tid >> 5;
    int cnt = __popc(__ballot_sync(0xffffffffu, valid));
    if (lane == 0) { wsum[warp] = v; wcnt[warp] = cnt; }
    __syncthreads();
    if (tid == 0) {
        long long vs = 0; int cs = 0;
#pragma unroll
        for (int i = 0; i < QBLK / 32; i++) { vs += wsum[i]; cs += wcnt[i]; }
        g_psum[blockIdx.x] = vs;
        g_pcnt[blockIdx.x] = cs;
    }
}

__global__ __launch_bounds__(NSCAN) void final_kernel(float* __restrict__ out) {
    __shared__ long long s0[NSCAN / 2], s1[NSCAN / 2];
    __shared__ int c0[NSCAN / 2], c1[NSCAN / 2];
    int t = threadIdx.x;
    if (t < NSCAN / 2) { s0[t] = g_psum[t]; c0[t] = g_pcnt[t]; }
    else { s1[t - NSCAN / 2] = g_psum[t]; c1[t - NSCAN / 2] = g_pcnt[t]; }
    __syncthreads();
    for (int o = NSCAN / 4; o; o >>= 1) {
        if (t < o) { s0[t] += s0[t + o]; c0[t] += c0[t + o]; }
        else if (t >= NSCAN / 2 && t < NSCAN / 2 + o) {
            int u = t - NSCAN / 2;
            s1[u] += s1[u + o]; c1[u] += c1[u + o];
        }
        __syncthreads();
    }
    if (t == 0) {
        double S0 = (double)s0[0] / 4294967296.0;
        double S1 = (double)s1[0] / 4294967296.0;
        float l0 = (float)(S0 / (3.0 * (double)max(c0[0], 1)));
        float l1 = (float)(S1 / (3.0 * (double)max(c1[0], 1)));
        out[0] = 0.5f * (l0 + l1);
    }
}

extern "C" void kernel_launch(void* const* d_in, const int* in_sizes, int n_in,
                              void* d_out, int out_size) {
    const float* src = (const float*)d_in[0];   // source_pc [2,64,2048,3]
    const float* tgt = (const float*)d_in[1];   // target_pc [2,3,64,2048]

    init_kernel<<<1, 1024>>>();
    hist_kernel<<<NB * NPTS / 256, 256>>>(src, tgt);
    prefix_kernel<<<1, NBINS>>>();
    scatter_kernel<<<NB * NPTS / 256, 256>>>(src, tgt);
    scan_kernel<<<NSCAN, QBLK>>>();
    final_kernel<<<1, NSCAN>>>((float*)d_out);
}

// round 7
// speedup vs baseline: 5.0991x; 1.8564x over previous
#include <cuda_runtime.h>

// knnLoss via exact x-sorted, window-bounded, split-k KNN.
// init -> hist(x-bin) -> prefix -> counting scatter (targets SoA, queries packed)
// -> phase A: home-tile scan => per-query top3 bound + per-group tile window
// -> phase B: 4-way split-k scan of window tiles (pruned, partial top3)
// -> merge (home + splits, exact) -> deterministic final reduce.

#define NPTS   16384
#define NB     2
#define NBINS  512
#define XMIN   (-4.5f)
#define BINSCL (NBINS / 9.0f)
#define WBIN   (9.0f / NBINS)
#define TILE   512
#define NTILES (NPTS / TILE)       // 32
#define QBLK   256                 // queries per group
#define NGRP   (NB * NPTS / QBLK)  // 128 groups
#define SPLIT  4

__device__ int       g_thist[NB * NBINS];
__device__ int       g_qhist[NB * NBINS];
__device__ int       g_tbase[NB * NBINS];
__device__ int       g_tcur [NB * NBINS];
__device__ int       g_qcur [NB * NBINS];
__device__ float     g_sx[NB * NPTS];
__device__ float     g_sy[NB * NPTS];
__device__ float     g_sz[NB * NPTS];
__device__ float     g_sw[NB * NPTS];
__device__ float4    g_q [NB * NPTS];
__device__ float     g_phome[NB * NPTS * 3];
__device__ float     g_psplit[SPLIT * NB * NPTS * 3];
__device__ int       g_glo[NGRP];
__device__ int       g_ghi[NGRP];
__device__ int       g_ghome[NGRP];
__device__ long long g_psum[NGRP];
__device__ int       g_pcnt[NGRP];

#define FMA2(d, a, b, c) \
    asm("fma.rn.f32x2 %0, %1, %2, %3;" : "=l"(d) : "l"(a), "l"(b), "l"(c))
#define UNPK2(lo, hi, v) \
    asm("mov.b64 {%0, %1}, %2;" : "=f"(lo), "=f"(hi) : "l"(v))
#define DUP2(d, f) \
    asm("mov.b64 %0, {%1, %1};" : "=l"(d) : "f"(f))

__device__ __forceinline__ int xbin(float x) {
    int b = (int)((x - XMIN) * BINSCL);
    return min(max(b, 0), NBINS - 1);
}

__device__ __forceinline__ void top3_insert(float r, float& b0, float& b1, float& b2) {
    float m1 = fmaxf(r, b1);
    float m0 = fmaxf(r, b0);
    b2 = fminf(b2, m1);
    b1 = fminf(b1, m0);
    b0 = fminf(b0, r);
}

// conservative tile x-bounds from first/last entry bins (edge bins -> +-inf)
__device__ __forceinline__ void tile_bounds(int b, int t, float& xlo, float& xhi) {
    int binf = xbin(g_sx[b * NPTS + t * TILE]);
    int binl = xbin(g_sx[b * NPTS + t * TILE + TILE - 1]);
    xlo = (binf == 0)         ? -1e30f : XMIN + binf * WBIN;
    xhi = (binl == NBINS - 1) ?  1e30f : XMIN + (binl + 1) * WBIN;
}

__global__ void init_kernel() {
    int t = threadIdx.x;
    if (t < NB * NBINS) { g_thist[t] = 0; g_qhist[t] = 0; }
}

__global__ void hist_kernel(const float* __restrict__ src,
                            const float* __restrict__ tgt) {
    int i = blockIdx.x * blockDim.x + threadIdx.x;
    int b = i >> 14;
    int n = i & (NPTS - 1);
    int h = n >> 9;
    int w = n & 511;
    long sb = (((long)b * 64 + 2 * h) * 2048 + 4 * w) * 3;
    float sx = src[sb];
    long tb = (long)b * 3 * 64 * 2048 + (long)(2 * h) * 2048 + 4 * w;
    float tx = tgt[tb];
    atomicAdd(&g_thist[b * NBINS + xbin(tx)], 1);
    atomicAdd(&g_qhist[b * NBINS + xbin(sx)], 1);
}

__global__ __launch_bounds__(NBINS) void prefix_kernel() {
    __shared__ int sh[NBINS];
    int t = threadIdx.x;
    for (int a = 0; a < 4; a++) {
        int v = (a < 2) ? g_thist[a * NBINS + t] : g_qhist[(a - 2) * NBINS + t];
        sh[t] = v;
        __syncthreads();
        for (int o = 1; o < NBINS; o <<= 1) {
            int u = (t >= o) ? sh[t - o] : 0;
            __syncthreads();
            sh[t] += u;
            __syncthreads();
        }
        int excl = sh[t] - v;
        if (a < 2) {
            g_tbase[a * NBINS + t] = excl;
            g_tcur [a * NBINS + t] = excl;
        } else {
            g_qcur[(a - 2) * NBINS + t] = excl;
        }
        __syncthreads();
    }
}

__global__ void scatter_kernel(const float* __restrict__ src,
                               const float* __restrict__ tgt) {
    int i = blockIdx.x * blockDim.x + threadIdx.x;
    int b = i >> 14;
    int n = i & (NPTS - 1);
    int h = n >> 9;
    int w = n & 511;

    long tb = (long)b * 3 * 64 * 2048 + (long)(2 * h) * 2048 + 4 * w;
    float tx = tgt[tb];
    float ty = tgt[tb + 64 * 2048];
    float tz = tgt[tb + 2L * 64 * 2048];
    bool  vt = (tx != 0.0f) || (ty != 0.0f) || (tz != 0.0f);
    float tw;
    if (vt) tw = tx * tx + ty * ty + tz * tz;
    else { tx = 0.0f; ty = 0.0f; tz = 0.0f; tw = 1e20f; }
    int tpos = atomicAdd(&g_tcur[b * NBINS + xbin(tx)], 1);
    int ts = b * NPTS + tpos;
    g_sx[ts] = tx; g_sy[ts] = ty; g_sz[ts] = tz; g_sw[ts] = tw;

    long sb = (((long)b * 64 + 2 * h) * 2048 + 4 * w) * 3;
    float sx = src[sb + 0];
    float sy = src[sb + 1];
    float sz = src[sb + 2];
    bool  vs = (sx != 0.0f) || (sy != 0.0f) || (sz != 0.0f);
    float sq = sx * sx + sy * sy + sz * sz;
    int qpos = atomicAdd(&g_qcur[b * NBINS + xbin(sx)], 1);
    g_q[b * NPTS + qpos] = make_float4(-2.0f * sx, -2.0f * sy, -2.0f * sz,
                                       vs ? sq : -1.0f);
}

// one tile scan: inserts into (b0,b1,b2) with cap filter
__device__ __forceinline__ void scan_tile(
    int base, int tid,
    ulonglong2* s_x, ulonglong2* s_y, ulonglong2* s_z, ulonglong2* s_w,
    unsigned long long qx, unsigned long long qy, unsigned long long qz,
    float& b0, float& b1, float& b2, float& bcap)
{
    const float4* px = (const float4*)(g_sx + base);
    const float4* py = (const float4*)(g_sy + base);
    const float4* pz = (const float4*)(g_sz + base);
    const float4* pw = (const float4*)(g_sw + base);
    if (tid < TILE / 4) {
        float4 vx = px[tid]; s_x[tid] = *(const ulonglong2*)&vx;
        float4 vy = py[tid]; s_y[tid] = *(const ulonglong2*)&vy;
    } else {
        int i2 = tid - TILE / 4;
        float4 vz = pz[i2]; s_z[i2] = *(const ulonglong2*)&vz;
        float4 vw = pw[i2]; s_w[i2] = *(const ulonglong2*)&vw;
    }
    __syncthreads();

#pragma unroll 4
    for (int j = 0; j < TILE / 4; j++) {
        ulonglong2 xv = s_x[j];
        ulonglong2 yv = s_y[j];
        ulonglong2 zv = s_z[j];
        ulonglong2 wv = s_w[j];
        unsigned long long rA, rB;
        FMA2(rA, qx, xv.x, wv.x);
        FMA2(rB, qx, xv.y, wv.y);
        FMA2(rA, qy, yv.x, rA);
        FMA2(rB, qy, yv.y, rB);
        FMA2(rA, qz, zv.x, rA);
        FMA2(rB, qz, zv.y, rB);
        float r0, r1, r2, r3;
        UNPK2(r0, r1, rA);
        UNPK2(r2, r3, rB);
        float m = fminf(fminf(r0, r1), fminf(r2, r3));
        if (m < bcap) {
            top3_insert(r0, b0, b1, b2);
            top3_insert(r1, b0, b1, b2);
            top3_insert(r2, b0, b1, b2);
            top3_insert(r3, b0, b1, b2);
            bcap = fminf(bcap, b2);
        }
    }
    __syncthreads();
}

__global__ __launch_bounds__(QBLK) void phaseA_kernel() {
    __shared__ ulonglong2 s_x[TILE / 4], s_y[TILE / 4], s_z[TILE / 4], s_w[TILE / 4];
    __shared__ float stlo[NTILES], sthi[NTILES];
    __shared__ float sA[QBLK / 32], sB[QBLK / 32];
    __shared__ int sh_home;

    int tid = threadIdx.x;
    int grp = blockIdx.x;
    int b   = grp >> 6;
    int qi  = b * NPTS + (grp & 63) * QBLK + tid;

    float4 s  = g_q[qi];
    float  xq = -0.5f * s.x;
    bool   valid = (s.w >= 0.0f);
    float  sq = fmaxf(s.w, 0.0f);
    unsigned long long qx, qy, qz;
    DUP2(qx, s.x); DUP2(qy, s.y); DUP2(qz, s.z);

    if (tid < NTILES) {
        float lo, hi;
        tile_bounds(b, tid, lo, hi);
        stlo[tid] = lo; sthi[tid] = hi;
    }
    if (tid == QBLK / 2)
        sh_home = min(g_tbase[b * NBINS + xbin(xq)] >> 9, NTILES - 1);
    __syncthreads();
    int home = sh_home;

    float b0 = 3e38f, b1 = 3e38f, b2 = 3e38f, bcap = 3e38f;
    scan_tile(b * NPTS + home * TILE, tid, s_x, s_y, s_z, s_w,
              qx, qy, qz, b0, b1, b2, bcap);

    // per-group window from per-query radius bound
    float rq = sqrtf(fmaxf(b2 + sq, 0.0f));
    float A  = valid ? xq - rq : 1e30f;
    float Bv = valid ? xq + rq : -1e30f;
#pragma unroll
    for (int o = 16; o; o >>= 1) {
        A  = fminf(A,  __shfl_xor_sync(0xffffffffu, A,  o));
        Bv = fmaxf(Bv, __shfl_xor_sync(0xffffffffu, Bv, o));
    }
    int lane = tid & 31, warp = tid >> 5;
    if (lane == 0) { sA[warp] = A; sB[warp] = Bv; }
    __syncthreads();
    if (tid == 0) {
        float mA = sA[0], mB = sB[0];
#pragma unroll
        for (int i = 1; i < QBLK / 32; i++) {
            mA = fminf(mA, sA[i]);
            mB = fmaxf(mB, sB[i]);
        }
        int tLo = NTILES, tHi = -1;
        for (int t = 0; t < NTILES; t++)
            if (sthi[t] >= mA) { tLo = t; break; }
        for (int t = NTILES - 1; t >= 0; t--)
            if (stlo[t] <= mB) { tHi = t; break; }
        g_glo[grp] = tLo;
        g_ghi[grp] = tHi;
        g_ghome[grp] = home;
    }

    int o = qi * 3;
    g_phome[o + 0] = b0;
    g_phome[o + 1] = b1;
    g_phome[o + 2] = b2;
}

__global__ __launch_bounds__(QBLK) void phaseB_kernel() {
    __shared__ ulonglong2 s_x[TILE / 4], s_y[TILE / 4], s_z[TILE / 4], s_w[TILE / 4];
    __shared__ float sh_xlo, sh_xhi;

    int tid = threadIdx.x;
    int grp = blockIdx.x;
    int sp  = blockIdx.y;
    int b   = grp >> 6;
    int qi  = b * NPTS + (grp & 63) * QBLK + tid;

    float4 s  = g_q[qi];
    float  xq = -0.5f * s.x;
    bool   valid = (s.w >= 0.0f);
    float  sq = fmaxf(s.w, 0.0f);
    unsigned long long qx, qy, qz;
    DUP2(qx, s.x); DUP2(qy, s.y); DUP2(qz, s.z);

    float bhome = g_phome[qi * 3 + 2];
    float b0 = 3e38f, b1 = 3e38f, b2 = 3e38f;
    float bcap = bhome;                 // prune bound (never double-counts home)

    int tLo = g_glo[grp], tHi = g_ghi[grp], home = g_ghome[grp];

    for (int t = tLo + sp; t <= tHi; t += SPLIT) {
        if (t == home) continue;
        int base = b * NPTS + t * TILE;
        if (tid == 0) {
            float lo, hi;
            tile_bounds(b, t, lo, hi);
            sh_xlo = lo; sh_xhi = hi;
        }
        __syncthreads();
        float xlo = sh_xlo, xhi = sh_xhi;
        float rq = sqrtf(fmaxf(bcap + sq, 0.0f));
        bool need = valid && (xq + rq >= xlo) && (xq - rq <= xhi);
        if (__syncthreads_or(need))
            scan_tile(base, tid, s_x, s_y, s_z, s_w, qx, qy, qz, b0, b1, b2, bcap);
    }

    int o = (sp * NB * NPTS + qi) * 3;
    g_psplit[o + 0] = b0;
    g_psplit[o + 1] = b1;
    g_psplit[o + 2] = b2;
}

__global__ __launch_bounds__(QBLK) void merge_kernel() {
    int tid = threadIdx.x;
    int grp = blockIdx.x;
    int b   = grp >> 6;
    int qi  = b * NPTS + (grp & 63) * QBLK + tid;

    float4 s = g_q[qi];
    bool  valid = (s.w >= 0.0f);
    float sq = fmaxf(s.w, 0.0f);

    float b0 = g_phome[qi * 3 + 0];
    float b1 = g_phome[qi * 3 + 1];
    float b2 = g_phome[qi * 3 + 2];
#pragma unroll
    for (int sp = 0; sp < SPLIT; sp++) {
        int o = (sp * NB * NPTS + qi) * 3;
#pragma unroll
        for (int k = 0; k < 3; k++)
            top3_insert(g_psplit[o + k], b0, b1, b2);
    }

    float wgt  = valid ? 1.0f : 0.0f;
    float dsum = sqrtf(fmaxf(b0 + sq, 0.0f))
               + sqrtf(fmaxf(b1 + sq, 0.0f))
               + sqrtf(fmaxf(b2 + sq, 0.0f));

    long long v = __float2ll_rn(fminf(wgt * dsum, 1e5f) * 4294967296.0f);
#pragma unroll
    for (int o = 16; o; o >>= 1)
        v += __shfl_down_sync(0xffffffffu, v, o);

    __shared__ long long wsum[QBLK / 32];
    __shared__ int       wcnt[QBLK / 32];
    int lane = tid & 31, warp = tid >> 5;
    int cnt = __popc(__ballot_sync(0xffffffffu, valid));
    if (lane == 0) { wsum[warp] = v; wcnt[warp] = cnt; }
    __syncthreads();
    if (tid == 0) {
        long long vs = 0; int cs = 0;
#pragma unroll
        for (int i = 0; i < QBLK / 32; i++) { vs += wsum[i]; cs += wcnt[i]; }
        g_psum[blockIdx.x] = vs;
        g_pcnt[blockIdx.x] = cs;
    }
}

__global__ __launch_bounds__(NGRP) void final_kernel(float* __restrict__ out) {
    __shared__ long long s0[NGRP / 2], s1[NGRP / 2];
    __shared__ int c0[NGRP / 2], c1[NGRP / 2];
    int t = threadIdx.x;
    if (t < NGRP / 2) { s0[t] = g_psum[t]; c0[t] = g_pcnt[t]; }
    else { s1[t - NGRP / 2] = g_psum[t]; c1[t - NGRP / 2] = g_pcnt[t]; }
    __syncthreads();
    for (int o = NGRP / 4; o; o >>= 1) {
        if (t < o) { s0[t] += s0[t + o]; c0[t] += c0[t + o]; }
        else if (t >= NGRP / 2 && t < NGRP / 2 + o) {
            int u = t - NGRP / 2;
            s1[u] += s1[u + o]; c1[u] += c1[u + o];
        }
        __syncthreads();
    }
    if (t == 0) {
        double S0 = (double)s0[0] / 4294967296.0;
        double S1 = (double)s1[0] / 4294967296.0;
        float l0 = (float)(S0 / (3.0 * (double)max(c0[0], 1)));
        float l1 = (float)(S1 / (3.0 * (double)max(c1[0], 1)));
        out[0] = 0.5f * (l0 + l1);
    }
}

extern "C" void kernel_launch(void* const* d_in, const int* in_sizes, int n_in,
                              void* d_out, int out_size) {
    const float* src = (const float*)d_in[0];   // source_pc [2,64,2048,3]
    const float* tgt = (const float*)d_in[1];   // target_pc [2,3,64,2048]

    init_kernel<<<1, 1024>>>();
    hist_kernel<<<NB * NPTS / 256, 256>>>(src, tgt);
    prefix_kernel<<<1, NBINS>>>();
    scatter_kernel<<<NB * NPTS / 256, 256>>>(src, tgt);
    phaseA_kernel<<<NGRP, QBLK>>>();
    dim3 gb(NGRP, SPLIT);
    phaseB_kernel<<<gb, QBLK>>>();
    merge_kernel<<<NGRP, QBLK>>>();
    final_kernel<<<1, NGRP>>>((float*)d_out);
}